// round 11
// baseline (speedup 1.0000x reference)
#include <cuda_runtime.h>
#include <cuda_fp16.h>
#include <cstdint>

// Problem constants
#define BN 4
#define CN 2048
#define HN 24
#define WN 24
#define LN 576   // H*W

// GEMM tile constants
#define TBM 128
#define TBN 128
#define TBK 32
#define AROW  40    // !TRANSA A smem row stride in halves (80B = 5x16B, odd phase)
#define ATROW 136   // TRANSA  A smem row stride in halves (272B = 17x16B)
#define BROW  136   // B smem row stride in halves

// ---------------- scratch (device globals; no allocation allowed) -----------
__device__ __half g_q[(long)BN * 2 * CN * LN];  // [B][2C][L]: rows 0..C-1 = q, C..2C-1 = T_part
__device__ __half g_k[(long)BN * CN * LN];      // [B][C][L]
__device__ __half g_pt[(long)BN * CN * LN];     // part_target (half)
__device__ __half g_pr[(long)BN * CN * LN];     // part_ref (half)
__device__ __half g_wq[(long)CN * CN];
__device__ __half g_wk[(long)CN * CN];
__device__ __half g_wt[(long)CN * 2 * CN];
__device__ float g_gram[(long)BN * LN * LN];    // [B][L_ref][L_tgt]
__device__ float g_n2[2 * BN * LN];
__device__ float g_pn[2 * BN * LN];
__device__ float g_rstar[BN * LN];
__device__ int   g_arg[BN * LN];
__device__ int   g_idx[BN * LN * 9];

__device__ __forceinline__ unsigned su(const void* p) {
    return (unsigned)__cvta_generic_to_shared(p);
}
#define CP16(d, s, sz) \
    asm volatile("cp.async.cg.shared.global [%0], [%1], 16, %2;" \
                 :: "r"(d), "l"(s), "r"(sz))

__device__ __forceinline__ void ldm_x4(uint32_t* r, unsigned a) {
    asm volatile("ldmatrix.sync.aligned.m8n8.x4.shared.b16 {%0,%1,%2,%3}, [%4];"
                 : "=r"(r[0]), "=r"(r[1]), "=r"(r[2]), "=r"(r[3]) : "r"(a));
}
__device__ __forceinline__ void ldm_x4_t(uint32_t* r, unsigned a) {
    asm volatile("ldmatrix.sync.aligned.m8n8.x4.trans.shared.b16 {%0,%1,%2,%3}, [%4];"
                 : "=r"(r[0]), "=r"(r[1]), "=r"(r[2]), "=r"(r[3]) : "r"(a));
}
#define MMA16(d, a, b0, b1) \
    asm volatile( \
        "mma.sync.aligned.m16n8k16.row.col.f32.f16.f16.f32 " \
        "{%0,%1,%2,%3},{%4,%5,%6,%7},{%8,%9},{%0,%1,%2,%3};" \
        : "+f"((d)[0]), "+f"((d)[1]), "+f"((d)[2]), "+f"((d)[3]) \
        : "r"((a)[0]), "r"((a)[1]), "r"((a)[2]), "r"((a)[3]), \
          "r"(b0), "r"(b1))

// ---------------- fp16 tensor-core GEMM (mma.sync m16n8k16) ------------------
// C[M, LN] = op(A)[M,K] * B[K,LN] (half operands, f32 accumulate).
// op(A)=A row-major [M,K] if !TRANSA, else A stored [K,M] row-major.
// B row-major [K,LN]. K % 32 == 0.
// MODE 0: out(half) = half(acc + bias[row])
// MODE 1: out(f32)  = acc
// MODE 2: out(f32)  = (acc + bias[row]) * Sv[b*LN+col] + resid[b*sR + row*LN + col]
template<bool TRANSA, int MODE>
__global__ __launch_bounds__(256, 2)
void gemm_h(const __half* __restrict__ A, const __half* __restrict__ Bm,
            void* __restrict__ Cm_, int M, int K,
            long sA, long sB, long sC,
            const float* __restrict__ bias,
            const float* __restrict__ Sv,
            const float* __restrict__ resid, long sR)
{
    extern __shared__ __half smem[];
    const int ASZ = TRANSA ? TBK * ATROW : TBM * AROW;
    const int BSZ = TBK * BROW;
    const int BUF = ASZ + BSZ;

    const int b = blockIdx.z;
    A  += (long)b * sA;
    Bm += (long)b * sB;

    const int m0 = blockIdx.y * TBM;
    const int n0 = blockIdx.x * TBN;
    const int t  = threadIdx.x;
    const int lane = t & 31;
    const int w = t >> 5;
    const int wm = (w >> 1) * 32;
    const int wn = (w & 1) * 64;
    const int gid = lane >> 2;
    const int tig = lane & 3;

    float acc[2][8][4];
#pragma unroll
    for (int mt = 0; mt < 2; mt++)
#pragma unroll
        for (int nt = 0; nt < 8; nt++)
#pragma unroll
            for (int r = 0; r < 4; r++) acc[mt][nt][r] = 0.f;

    auto stage = [&](int kt, int buf) {
        __half* as = smem + buf * BUF;
        __half* bs = as + ASZ;
        const int k0 = kt * TBK;
        if (!TRANSA) {
#pragma unroll
            for (int i = 0; i < 2; i++) {
                int idx = t + i * 256;
                int m = idx >> 2, ch = idx & 3;        // 4 chunks x 8 halves
                const __half* src = A + (long)(m0 + m) * K + k0 + ch * 8;
                unsigned sz = (m0 + m < M) ? 16u : 0u;
                CP16(su(as + m * AROW + ch * 8), src, sz);
            }
        } else {
#pragma unroll
            for (int i = 0; i < 2; i++) {
                int idx = t + i * 256;
                int kk = idx >> 4, ch = idx & 15;
                const __half* src = A + (long)(k0 + kk) * M + m0 + ch * 8;
                unsigned sz = (m0 + ch * 8 < M) ? 16u : 0u;
                CP16(su(as + kk * ATROW + ch * 8), src, sz);
            }
        }
#pragma unroll
        for (int i = 0; i < 2; i++) {
            int idx = t + i * 256;
            int kk = idx >> 4, ch = idx & 15;
            const __half* src = Bm + (long)(k0 + kk) * LN + n0 + ch * 8;
            unsigned sz = (n0 + ch * 8 < LN) ? 16u : 0u;
            CP16(su(bs + kk * BROW + ch * 8), src, sz);
        }
        asm volatile("cp.async.commit_group;");
    };

    const int nk = K / TBK;
    stage(0, 0);
    stage(1, 1);

    for (int it = 0; it < nk; it++) {
        if (it + 1 < nk)
            asm volatile("cp.async.wait_group 1;");
        else
            asm volatile("cp.async.wait_group 0;");
        __syncthreads();

        const __half* as = smem + (it % 3) * BUF;
        const __half* bs = as + ASZ;

#pragma unroll
        for (int ks = 0; ks < 2; ks++) {
            const int k = ks * 16;
            uint32_t af[2][4], bf[4][4];
            if (!TRANSA) {
#pragma unroll
                for (int mt = 0; mt < 2; mt++) {
                    unsigned a = su(as + (wm + mt * 16 + (lane & 15)) * AROW
                                       + k + (lane >> 4) * 8);
                    ldm_x4(af[mt], a);
                }
            } else {
#pragma unroll
                for (int mt = 0; mt < 2; mt++) {
                    unsigned a = su(as + (k + (lane & 7) + ((lane >> 4) & 1) * 8) * ATROW
                                       + wm + mt * 16 + ((lane >> 3) & 1) * 8);
                    ldm_x4_t(af[mt], a);
                }
            }
#pragma unroll
            for (int g = 0; g < 4; g++) {
                unsigned a = su(bs + (k + (lane & 7) + ((lane >> 3) & 1) * 8) * BROW
                                   + wn + g * 16 + ((lane >> 4) & 1) * 8);
                ldm_x4_t(bf[g], a);
            }
#pragma unroll
            for (int mt = 0; mt < 2; mt++)
#pragma unroll
                for (int nt = 0; nt < 8; nt++) {
                    int g = nt >> 1, h = (nt & 1) * 2;
                    MMA16(acc[mt][nt], af[mt], bf[g][h], bf[g][h + 1]);
                }
        }
        if (it + 2 < nk) stage(it + 2, (it + 2) % 3);
    }

    // ---- epilogue ----
#pragma unroll
    for (int mt = 0; mt < 2; mt++) {
#pragma unroll
        for (int rp = 0; rp < 2; rp++) {
            int row = m0 + wm + mt * 16 + gid + rp * 8;
            if (row >= M) continue;
            float bv = (MODE != 1) ? bias[row] : 0.f;
#pragma unroll
            for (int nt = 0; nt < 8; nt++) {
                int col = n0 + wn + nt * 8 + tig * 2;
                if (col >= LN) continue;
                float v0 = acc[mt][nt][rp * 2 + 0];
                float v1 = acc[mt][nt][rp * 2 + 1];
                if (MODE == 0) {
                    __half* C = (__half*)Cm_ + (long)b * sC;
                    *(__half2*)(C + (long)row * LN + col) =
                        __floats2half2_rn(v0 + bv, v1 + bv);
                } else if (MODE == 1) {
                    float* C = (float*)Cm_ + (long)b * sC;
                    *(float2*)(C + (long)row * LN + col) = make_float2(v0, v1);
                } else {
                    float* C = (float*)Cm_ + (long)b * sC;
                    const float* rs = resid + (long)b * sR + (long)row * LN + col;
                    float2 rv = *(const float2*)rs;
                    float2 o;
                    o.x = (v0 + bv) * Sv[b * LN + col + 0] + rv.x;
                    o.y = (v1 + bv) * Sv[b * LN + col + 1] + rv.y;
                    *(float2*)(C + (long)row * LN + col) = o;
                }
            }
        }
    }
}

// ---------------- f32 -> f16 conversion (wide: 8 floats / thread / iter) ----
__global__ __launch_bounds__(256)
void tohalf_kernel(const float4* __restrict__ src,
                   uint4* __restrict__ dst, long n8)
{
    long i = (long)blockIdx.x * blockDim.x + threadIdx.x;
    long stride = (long)gridDim.x * blockDim.x;
    for (; i < n8; i += stride) {
        float4 a = src[i * 2 + 0];
        float4 b = src[i * 2 + 1];
        __half2 h0 = __floats2half2_rn(a.x, a.y);
        __half2 h1 = __floats2half2_rn(a.z, a.w);
        __half2 h2 = __floats2half2_rn(b.x, b.y);
        __half2 h3 = __floats2half2_rn(b.z, b.w);
        uint4 o;
        o.x = *(uint32_t*)&h0; o.y = *(uint32_t*)&h1;
        o.z = *(uint32_t*)&h2; o.w = *(uint32_t*)&h3;
        dst[i] = o;
    }
}

// ---------------- pixel squared norms ---------------------------------------
__global__ void pixnorm_kernel()
{
    const int b = blockIdx.y;
    const int which = blockIdx.z;   // 0 = k, 1 = q
    const int tid = threadIdx.x;
    const int lane = tid & 31;
    const int cs = tid >> 5;
    const int l = blockIdx.x * 32 + lane;
    const __half* src = which ? (g_q + (long)b * 2 * CN * LN)
                              : (g_k + (long)b * CN * LN);
    float s = 0.f;
    for (int c = cs; c < CN; c += 8) {
        float v = __half2float(src[(long)c * LN + l]);
        s += v * v;
    }
    __shared__ float red[256];
    red[tid] = s;
    __syncthreads();
    for (int off = 128; off >= 32; off >>= 1) {
        if (tid < off) red[tid] += red[tid + off];
        __syncthreads();
    }
    if (tid < 32) g_n2[which * BN * LN + b * LN + l] = red[tid];
}

// ---------------- patch norms ------------------------------------------------
__global__ void patchnorm_kernel()
{
    int idx = blockIdx.x * blockDim.x + threadIdx.x;
    if (idx >= 2 * BN * LN) return;
    int which = idx / (BN * LN);
    int rem = idx % (BN * LN);
    int b = rem / LN;
    int l = rem % LN;
    int li = l / WN, lj = l % WN;
    const float* n2 = g_n2 + which * BN * LN + b * LN;
    float s = 0.f;
#pragma unroll
    for (int di = -1; di <= 1; di++)
#pragma unroll
        for (int dj = -1; dj <= 1; dj++) {
            int i2 = li + di, j2 = lj + dj;
            if (i2 >= 0 && i2 < HN && j2 >= 0 && j2 < WN)
                s += n2[i2 * WN + j2];
        }
    g_pn[idx] = fmaxf(sqrtf(s), 1e-12f);
}

// ---------------- R + argmax over ref positions ------------------------------
__global__ void rstar_kernel()
{
    const int m = blockIdx.x;
    const int b = blockIdx.y;
    const int mi = m / WN, mj = m % WN;
    const float* G = g_gram + (long)b * LN * LN;
    const float* pnk = g_pn + b * LN;
    const int tid = threadIdx.x;

    float best = -1e30f;
    int barg = 0;
    for (int l = tid; l < LN; l += 128) {
        int li = l / WN, lj = l % WN;
        float s = 0.f;
#pragma unroll
        for (int di = -1; di <= 1; di++)
#pragma unroll
            for (int dj = -1; dj <= 1; dj++) {
                int li2 = li + di, lj2 = lj + dj;
                int mi2 = mi + di, mj2 = mj + dj;
                if (li2 >= 0 && li2 < HN && lj2 >= 0 && lj2 < WN &&
                    mi2 >= 0 && mi2 < HN && mj2 >= 0 && mj2 < WN) {
                    int off = di * WN + dj;
                    s += G[(long)(l + off) * LN + (m + off)];
                }
            }
        float v = s / pnk[l];
        if (v > best) { best = v; barg = l; }
    }
    __shared__ float sv[128];
    __shared__ int si[128];
    sv[tid] = best; si[tid] = barg;
    __syncthreads();
    for (int off = 64; off >= 1; off >>= 1) {
        if (tid < off) {
            if (sv[tid + off] > sv[tid] ||
                (sv[tid + off] == sv[tid] && si[tid + off] < si[tid])) {
                sv[tid] = sv[tid + off];
                si[tid] = si[tid + off];
            }
        }
        __syncthreads();
    }
    if (tid == 0) {
        g_rstar[b * LN + m] = sv[0] / g_pn[BN * LN + b * LN + m];
        g_arg[b * LN + m] = si[0];
    }
}

// ---------------- gather-index precompute ------------------------------------
__global__ void idx_kernel()
{
    int idx = blockIdx.x * blockDim.x + threadIdx.x;
    if (idx >= BN * LN) return;
    int b = idx / LN;
    int p = idx % LN;
    int pi = p / WN, pj = p % WN;
#pragma unroll
    for (int j = 0; j < 9; j++) {
        int di = j / 3 - 1, dj = j % 3 - 1;
        int mi = pi - di, mj = pj - dj;
        int id = -1;
        if (mi >= 0 && mi < HN && mj >= 0 && mj < WN) {
            int a = g_arg[b * LN + mi * WN + mj];
            int ai = a / WN + di, aj = a % WN + dj;
            if (ai >= 0 && ai < HN && aj >= 0 && aj < WN)
                id = ai * WN + aj;
        }
        g_idx[(long)(b * LN + p) * 9 + j] = id;
    }
}

// ---------------- build T_part (half) into second half of g_q ----------------
__global__ void tpart_kernel()
{
    const int c = blockIdx.x;
    const int b = blockIdx.y;
    const __half* krow = g_k + ((long)b * CN + c) * LN;
    const int* idxr = g_idx + (long)b * LN * 9;
    const int p = threadIdx.x;
    float s = 0.f;
#pragma unroll
    for (int j = 0; j < 9; j++) {
        int id = idxr[p * 9 + j];
        if (id >= 0) s += __half2float(krow[id]);
    }
    g_q[((long)b * 2 * CN + CN + c) * LN + p] = __float2half_rn(s * (1.f / 9.f));
}

// ---------------- host launch ------------------------------------------------
extern "C" void kernel_launch(void* const* d_in, const int* in_sizes, int n_in,
                              void* d_out, int out_size)
{
    const float* part_ref    = (const float*)d_in[0];
    const float* part_target = (const float*)d_in[1];
    const float* wq = (const float*)d_in[2];
    const float* bq = (const float*)d_in[3];
    const float* wk = (const float*)d_in[4];
    const float* bk = (const float*)d_in[5];
    const float* wt = (const float*)d_in[6];
    const float* bt = (const float*)d_in[7];
    float* out = (float*)d_out;

    __half *q_ptr, *k_ptr, *pt_h, *pr_h, *wq_h, *wk_h, *wt_h;
    float *g_ptr, *s_ptr;
    cudaGetSymbolAddress((void**)&q_ptr, g_q);
    cudaGetSymbolAddress((void**)&k_ptr, g_k);
    cudaGetSymbolAddress((void**)&pt_h,  g_pt);
    cudaGetSymbolAddress((void**)&pr_h,  g_pr);
    cudaGetSymbolAddress((void**)&wq_h,  g_wq);
    cudaGetSymbolAddress((void**)&wk_h,  g_wk);
    cudaGetSymbolAddress((void**)&wt_h,  g_wt);
    cudaGetSymbolAddress((void**)&g_ptr, g_gram);
    cudaGetSymbolAddress((void**)&s_ptr, g_rstar);

    // dynamic smem (3-stage), in bytes
    const int smemN = 3 * (TBM * AROW + TBK * BROW) * 2;   // 56832
    const int smemT = 3 * (TBK * ATROW + TBK * BROW) * 2;  // 52224
    cudaFuncSetAttribute(gemm_h<false, 0>,
        cudaFuncAttributeMaxDynamicSharedMemorySize, smemN);
    cudaFuncSetAttribute(gemm_h<true, 1>,
        cudaFuncAttributeMaxDynamicSharedMemorySize, smemT);
    cudaFuncSetAttribute(gemm_h<false, 2>,
        cudaFuncAttributeMaxDynamicSharedMemorySize, smemN);

    // 0) convert all GEMM operands to half (wide copies)
    {
        long n8q = (long)CN * CN / 8;
        tohalf_kernel<<<(int)((n8q + 255) / 256), 256>>>(
            (const float4*)wq, (uint4*)wq_h, n8q);
        tohalf_kernel<<<(int)((n8q + 255) / 256), 256>>>(
            (const float4*)wk, (uint4*)wk_h, n8q);
        long n8t = (long)CN * 2 * CN / 8;
        tohalf_kernel<<<(int)((n8t + 255) / 256), 256>>>(
            (const float4*)wt, (uint4*)wt_h, n8t);
        long n8f = (long)BN * CN * LN / 8;
        tohalf_kernel<<<(int)((n8f + 255) / 256), 256>>>(
            (const float4*)part_target, (uint4*)pt_h, n8f);
        tohalf_kernel<<<(int)((n8f + 255) / 256), 256>>>(
            (const float4*)part_ref, (uint4*)pr_h, n8f);
    }

    dim3 blk(256);
    const int NXT = (LN + TBN - 1) / TBN;   // 5

    // 1) q = half(wq @ part_target + bq)   -> g_q rows [0,C)
    gemm_h<false, 0><<<dim3(NXT, CN / TBM, BN), blk, smemN>>>(
        wq_h, pt_h, q_ptr, CN, CN,
        0L, (long)CN * LN, (long)2 * CN * LN, bq, nullptr, nullptr, 0L);

    // 2) k = half(wk @ part_ref + bk)      -> g_k
    gemm_h<false, 0><<<dim3(NXT, CN / TBM, BN), blk, smemN>>>(
        wk_h, pr_h, k_ptr, CN, CN,
        0L, (long)CN * LN, (long)CN * LN, bk, nullptr, nullptr, 0L);

    // 3) pixel squared norms
    pixnorm_kernel<<<dim3(LN / 32, BN, 2), 256>>>();
    // 4) patch norms
    patchnorm_kernel<<<(2 * BN * LN + 255) / 256, 256>>>();

    // 5) Gram: G[l,m] = sum_c k[c,l] q[c,m]   (f32 out)
    gemm_h<true, 1><<<dim3(NXT, (LN + TBM - 1) / TBM, BN), blk, smemT>>>(
        k_ptr, q_ptr, g_ptr, LN, CN,
        (long)CN * LN, (long)2 * CN * LN, (long)LN * LN,
        nullptr, nullptr, nullptr, 0L);

    // 6) R_star + argmax
    rstar_kernel<<<dim3(LN, BN), 128>>>();
    // 7) gather indices
    idx_kernel<<<(BN * LN + 255) / 256, 256>>>();
    // 8) T_part -> g_q rows [C,2C)
    tpart_kernel<<<dim3(CN, BN), LN>>>();

    // 9) final: out = (wt @ [q;T_part] + bt) * S + part_target
    gemm_h<false, 2><<<dim3(NXT, CN / TBM, BN), blk, smemN>>>(
        wt_h, q_ptr, out, CN, 2 * CN,
        0L, (long)2 * CN * LN, (long)CN * LN, bt, s_ptr, part_target,
        (long)CN * LN);
}

// round 14
// speedup vs baseline: 1.2137x; 1.2137x over previous
#include <cuda_runtime.h>
#include <cuda_fp16.h>
#include <cstdint>

// Problem constants
#define BN 4
#define CN 2048
#define HN 24
#define WN 24
#define LN 576    // H*W
#define BL 2304   // BN*LN

// GEMM tile constants
#define TBM 128
#define TBN 128
#define TBK 32
#define AROW  40    // !TRANSA A smem row stride in halves (80B = 5x16B, odd phase)
#define ATROW 136   // TRANSA  A smem row stride in halves (272B = 17x16B)
#define BROW  136   // B smem row stride in halves

// ---------------- scratch (device globals; no allocation allowed) -----------
__device__ __half g_q[(long)2 * CN * BL];   // [2C][BL]: rows 0..C-1 = q, C..2C-1 = T_part
__device__ __half g_k[(long)CN * BL];       // [C][BL]
__device__ __half g_pt[(long)CN * BL];      // part_target: [C][BL]
__device__ __half g_pr[(long)CN * BL];      // part_ref: [C][BL]
__device__ __half g_wq[(long)CN * CN];
__device__ __half g_wk[(long)CN * CN];
__device__ __half g_wt[(long)CN * 2 * CN];
__device__ float g_gram[(long)BN * LN * LN];  // [B][L_ref][L_tgt]
__device__ float g_n2[2 * BL];
__device__ float g_pn[2 * BL];
__device__ float g_rstar[BL];
__device__ int   g_arg[BL];
__device__ int   g_idx[BL * 9];

__device__ __forceinline__ unsigned su(const void* p) {
    return (unsigned)__cvta_generic_to_shared(p);
}
#define CP16(d, s, sz) \
    asm volatile("cp.async.cg.shared.global [%0], [%1], 16, %2;" \
                 :: "r"(d), "l"(s), "r"(sz))

__device__ __forceinline__ void ldm_x4(uint32_t* r, unsigned a) {
    asm volatile("ldmatrix.sync.aligned.m8n8.x4.shared.b16 {%0,%1,%2,%3}, [%4];"
                 : "=r"(r[0]), "=r"(r[1]), "=r"(r[2]), "=r"(r[3]) : "r"(a));
}
__device__ __forceinline__ void ldm_x4_t(uint32_t* r, unsigned a) {
    asm volatile("ldmatrix.sync.aligned.m8n8.x4.trans.shared.b16 {%0,%1,%2,%3}, [%4];"
                 : "=r"(r[0]), "=r"(r[1]), "=r"(r[2]), "=r"(r[3]) : "r"(a));
}
#define MMA16(d, a, b0, b1) \
    asm volatile( \
        "mma.sync.aligned.m16n8k16.row.col.f32.f16.f16.f32 " \
        "{%0,%1,%2,%3},{%4,%5,%6,%7},{%8,%9},{%0,%1,%2,%3};" \
        : "+f"((d)[0]), "+f"((d)[1]), "+f"((d)[2]), "+f"((d)[3]) \
        : "r"((a)[0]), "r"((a)[1]), "r"((a)[2]), "r"((a)[3]), \
          "r"(b0), "r"(b1))

// ---------------- fp16 tensor-core GEMM (mma.sync m16n8k16) ------------------
// C[M,N] = op(A)[M,K] * B[K,N] (half, f32 accumulate). op(A)=A row-major
// [M,K] ld=ldA if !TRANSA, else A stored [K,*] ld=ldA with M-window columns.
// MODE 0 (dual conv): blockIdx.z selects (A,B,C,bias) pair; out(half) = acc+bias[row]
// MODE 1 (gram):  z = batch; A += z*sA (col offset), B += z*sB, C += z*sC; out(f32)=acc
// MODE 2 (final): out f32 at [b][row][l] where col = b*LN + l;
//                 out = (acc + bias[row]) * Sv[col] + resid[b*CN*LN + row*LN + l]
template<bool TRANSA, int MODE>
__global__ __launch_bounds__(256, 2)
void gemm_h(const __half* __restrict__ A, const __half* __restrict__ Bm,
            void* __restrict__ Cm_, int M, int N, int K,
            int ldA, int ldB, int ldC,
            long sA, long sB, long sC,
            const __half* __restrict__ A1, const __half* __restrict__ B1,
            void* __restrict__ C1,
            const float* __restrict__ bias0, const float* __restrict__ bias1,
            const float* __restrict__ Sv, const float* __restrict__ resid)
{
    extern __shared__ __half smem[];
    const int ASZ = TRANSA ? TBK * ATROW : TBM * AROW;
    const int BSZ = TBK * BROW;
    const int BUF = ASZ + BSZ;

    const int z = blockIdx.z;
    const float* bias = bias0;
    if (MODE == 0 && z == 1) { A = A1; Bm = B1; Cm_ = C1; bias = bias1; }
    if (MODE == 1) { A += z * sA; Bm += z * sB; }

    const int m0 = blockIdx.y * TBM;
    const int n0 = blockIdx.x * TBN;
    const int t  = threadIdx.x;
    const int lane = t & 31;
    const int w = t >> 5;
    const int wm = (w >> 1) * 32;
    const int wn = (w & 1) * 64;
    const int gid = lane >> 2;
    const int tig = lane & 3;

    float acc[2][8][4];
#pragma unroll
    for (int mt = 0; mt < 2; mt++)
#pragma unroll
        for (int nt = 0; nt < 8; nt++)
#pragma unroll
            for (int r = 0; r < 4; r++) acc[mt][nt][r] = 0.f;

    auto stage = [&](int kt, int buf) {
        __half* as = smem + buf * BUF;
        __half* bs = as + ASZ;
        const int k0 = kt * TBK;
        if (!TRANSA) {
#pragma unroll
            for (int i = 0; i < 2; i++) {
                int idx = t + i * 256;
                int m = idx >> 2, ch = idx & 3;        // 4 chunks x 8 halves
                const __half* src = A + (long)(m0 + m) * ldA + k0 + ch * 8;
                CP16(su(as + m * AROW + ch * 8), src, 16u);
            }
        } else {
#pragma unroll
            for (int i = 0; i < 2; i++) {
                int idx = t + i * 256;
                int kk = idx >> 4, ch = idx & 15;
                const __half* src = A + (long)(k0 + kk) * ldA + m0 + ch * 8;
                unsigned sz = (m0 + ch * 8 < M) ? 16u : 0u;
                CP16(su(as + kk * ATROW + ch * 8), src, sz);
            }
        }
#pragma unroll
        for (int i = 0; i < 2; i++) {
            int idx = t + i * 256;
            int kk = idx >> 4, ch = idx & 15;
            const __half* src = Bm + (long)(k0 + kk) * ldB + n0 + ch * 8;
            unsigned sz = (n0 + ch * 8 < N) ? 16u : 0u;
            CP16(su(bs + kk * BROW + ch * 8), src, sz);
        }
        asm volatile("cp.async.commit_group;");
    };

    const int nk = K / TBK;
    stage(0, 0);
    stage(1, 1);

    for (int it = 0; it < nk; it++) {
        if (it + 1 < nk)
            asm volatile("cp.async.wait_group 1;");
        else
            asm volatile("cp.async.wait_group 0;");
        __syncthreads();

        const __half* as = smem + (it % 3) * BUF;
        const __half* bs = as + ASZ;

#pragma unroll
        for (int ks = 0; ks < 2; ks++) {
            const int k = ks * 16;
            uint32_t af[2][4], bf[4][4];
            if (!TRANSA) {
#pragma unroll
                for (int mt = 0; mt < 2; mt++) {
                    unsigned a = su(as + (wm + mt * 16 + (lane & 15)) * AROW
                                       + k + (lane >> 4) * 8);
                    ldm_x4(af[mt], a);
                }
            } else {
#pragma unroll
                for (int mt = 0; mt < 2; mt++) {
                    unsigned a = su(as + (k + (lane & 7) + ((lane >> 4) & 1) * 8) * ATROW
                                       + wm + mt * 16 + ((lane >> 3) & 1) * 8);
                    ldm_x4_t(af[mt], a);
                }
            }
#pragma unroll
            for (int g = 0; g < 4; g++) {
                unsigned a = su(bs + (k + (lane & 7) + ((lane >> 3) & 1) * 8) * BROW
                                   + wn + g * 16 + ((lane >> 4) & 1) * 8);
                ldm_x4_t(bf[g], a);
            }
#pragma unroll
            for (int mt = 0; mt < 2; mt++)
#pragma unroll
                for (int nt = 0; nt < 8; nt++) {
                    int g = nt >> 1, h = (nt & 1) * 2;
                    MMA16(acc[mt][nt], af[mt], bf[g][h], bf[g][h + 1]);
                }
        }
        if (it + 2 < nk) stage(it + 2, (it + 2) % 3);
    }

    // ---- epilogue ----
#pragma unroll
    for (int mt = 0; mt < 2; mt++) {
#pragma unroll
        for (int rp = 0; rp < 2; rp++) {
            int row = m0 + wm + mt * 16 + gid + rp * 8;
            if (MODE == 1 && row >= M) continue;
            float bv = (MODE != 1) ? bias[row] : 0.f;
#pragma unroll
            for (int nt = 0; nt < 8; nt++) {
                int col = n0 + wn + nt * 8 + tig * 2;
                float v0 = acc[mt][nt][rp * 2 + 0];
                float v1 = acc[mt][nt][rp * 2 + 1];
                if (MODE == 0) {
                    __half* C = (__half*)Cm_;
                    *(__half2*)(C + (long)row * ldC + col) =
                        __floats2half2_rn(v0 + bv, v1 + bv);
                } else if (MODE == 1) {
                    if (col >= N) continue;
                    float* C = (float*)Cm_ + z * sC;
                    *(float2*)(C + (long)row * ldC + col) = make_float2(v0, v1);
                } else {
                    int b = col / LN;
                    int l = col - b * LN;
                    float* C = (float*)Cm_ + (long)b * CN * LN + (long)row * LN + l;
                    const float* rs = resid + (long)b * CN * LN + (long)row * LN + l;
                    float2 rv = *(const float2*)rs;
                    float2 o;
                    o.x = (v0 + bv) * Sv[col + 0] + rv.x;
                    o.y = (v1 + bv) * Sv[col + 1] + rv.y;
                    *(float2*)C = o;
                }
            }
        }
    }
}

// ---------------- f32 -> f16 conversion (weights, wide grid-stride) ---------
__global__ __launch_bounds__(256)
void tohalf_kernel(const float4* __restrict__ src,
                   uint4* __restrict__ dst, long n8)
{
    long i = (long)blockIdx.x * blockDim.x + threadIdx.x;
    long stride = (long)gridDim.x * blockDim.x;
    for (; i < n8; i += stride) {
        float4 a = src[i * 2 + 0];
        float4 b = src[i * 2 + 1];
        __half2 h0 = __floats2half2_rn(a.x, a.y);
        __half2 h1 = __floats2half2_rn(a.z, a.w);
        __half2 h2 = __floats2half2_rn(b.x, b.y);
        __half2 h3 = __floats2half2_rn(b.z, b.w);
        uint4 o;
        o.x = *(uint32_t*)&h0; o.y = *(uint32_t*)&h1;
        o.z = *(uint32_t*)&h2; o.w = *(uint32_t*)&h3;
        dst[i] = o;
    }
}

// ---------------- f32 [B][C][L] -> f16 [C][B*L] ------------------------------
// grid (CN, BN, 2), block 576
__global__ void tohalf_fold_kernel(const float* __restrict__ pt,
                                   const float* __restrict__ pr)
{
    const int c = blockIdx.x;
    const int b = blockIdx.y;
    const float* src = blockIdx.z ? pr : pt;
    __half* dst = blockIdx.z ? g_pr : g_pt;
    const int l = threadIdx.x;
    float v = src[((long)b * CN + c) * LN + l];
    dst[(long)c * BL + b * LN + l] = __float2half_rn(v);
}

// ---------------- pixel squared norms ---------------------------------------
// grid (BL/32, 2), block 256 = 32 cols x 8 c-slices
__global__ void pixnorm_kernel()
{
    const int which = blockIdx.y;   // 0 = k, 1 = q
    const int tid = threadIdx.x;
    const int lane = tid & 31;
    const int cs = tid >> 5;
    const int j = blockIdx.x * 32 + lane;
    const __half* src = which ? g_q : g_k;
    float s = 0.f;
    for (int c = cs; c < CN; c += 8) {
        float v = __half2float(src[(long)c * BL + j]);
        s += v * v;
    }
    __shared__ float red[256];
    red[tid] = s;
    __syncthreads();
    for (int off = 128; off >= 32; off >>= 1) {
        if (tid < off) red[tid] += red[tid + off];
        __syncthreads();
    }
    if (tid < 32) g_n2[which * BL + j] = red[tid];
}

// ---------------- patch norms ------------------------------------------------
__global__ void patchnorm_kernel()
{
    int idx = blockIdx.x * blockDim.x + threadIdx.x;
    if (idx >= 2 * BL) return;
    int which = idx / BL;
    int rem = idx % BL;
    int b = rem / LN;
    int l = rem % LN;
    int li = l / WN, lj = l % WN;
    const float* n2 = g_n2 + which * BL + b * LN;
    float s = 0.f;
#pragma unroll
    for (int di = -1; di <= 1; di++)
#pragma unroll
        for (int dj = -1; dj <= 1; dj++) {
            int i2 = li + di, j2 = lj + dj;
            if (i2 >= 0 && i2 < HN && j2 >= 0 && j2 < WN)
                s += n2[i2 * WN + j2];
        }
    g_pn[idx] = fmaxf(sqrtf(s), 1e-12f);
}

// ---------------- R + argmax over ref positions ------------------------------
__global__ void rstar_kernel()
{
    const int m = blockIdx.x;
    const int b = blockIdx.y;
    const int mi = m / WN, mj = m % WN;
    const float* G = g_gram + (long)b * LN * LN;
    const float* pnk = g_pn + b * LN;
    const int tid = threadIdx.x;

    float best = -1e30f;
    int barg = 0;
    for (int l = tid; l < LN; l += 128) {
        int li = l / WN, lj = l % WN;
        float s = 0.f;
#pragma unroll
        for (int di = -1; di <= 1; di++)
#pragma unroll
            for (int dj = -1; dj <= 1; dj++) {
                int li2 = li + di, lj2 = lj + dj;
                int mi2 = mi + di, mj2 = mj + dj;
                if (li2 >= 0 && li2 < HN && lj2 >= 0 && lj2 < WN &&
                    mi2 >= 0 && mi2 < HN && mj2 >= 0 && mj2 < WN) {
                    int off = di * WN + dj;
                    s += G[(long)(l + off) * LN + (m + off)];
                }
            }
        float v = s / pnk[l];
        if (v > best) { best = v; barg = l; }
    }
    __shared__ float sv[128];
    __shared__ int si[128];
    sv[tid] = best; si[tid] = barg;
    __syncthreads();
    for (int off = 64; off >= 1; off >>= 1) {
        if (tid < off) {
            if (sv[tid + off] > sv[tid] ||
                (sv[tid + off] == sv[tid] && si[tid + off] < si[tid])) {
                sv[tid] = sv[tid + off];
                si[tid] = si[tid + off];
            }
        }
        __syncthreads();
    }
    if (tid == 0) {
        g_rstar[b * LN + m] = sv[0] / g_pn[BL + b * LN + m];
        g_arg[b * LN + m] = si[0];
    }
}

// ---------------- gather-index precompute ------------------------------------
__global__ void idx_kernel()
{
    int idx = blockIdx.x * blockDim.x + threadIdx.x;
    if (idx >= BL) return;
    int b = idx / LN;
    int p = idx % LN;
    int pi = p / WN, pj = p % WN;
#pragma unroll
    for (int j = 0; j < 9; j++) {
        int di = j / 3 - 1, dj = j % 3 - 1;
        int mi = pi - di, mj = pj - dj;
        int id = -1;
        if (mi >= 0 && mi < HN && mj >= 0 && mj < WN) {
            int a = g_arg[b * LN + mi * WN + mj];
            int ai = a / WN + di, aj = a % WN + dj;
            if (ai >= 0 && ai < HN && aj >= 0 && aj < WN)
                id = ai * WN + aj;
        }
        g_idx[(long)(b * LN + p) * 9 + j] = id;
    }
}

// ---------------- build T_part (half) into rows [C,2C) of g_q ----------------
// grid (CN, BN), block 576
__global__ void tpart_kernel()
{
    const int c = blockIdx.x;
    const int b = blockIdx.y;
    const __half* krow = g_k + (long)c * BL + b * LN;
    const int* idxr = g_idx + (long)b * LN * 9;
    const int p = threadIdx.x;
    float s = 0.f;
#pragma unroll
    for (int j = 0; j < 9; j++) {
        int id = idxr[p * 9 + j];
        if (id >= 0) s += __half2float(krow[id]);
    }
    g_q[(long)(CN + c) * BL + b * LN + p] = __float2half_rn(s * (1.f / 9.f));
}

// ---------------- host launch ------------------------------------------------
extern "C" void kernel_launch(void* const* d_in, const int* in_sizes, int n_in,
                              void* d_out, int out_size)
{
    const float* part_ref    = (const float*)d_in[0];
    const float* part_target = (const float*)d_in[1];
    const float* wq = (const float*)d_in[2];
    const float* bq = (const float*)d_in[3];
    const float* wk = (const float*)d_in[4];
    const float* bk = (const float*)d_in[5];
    const float* wt = (const float*)d_in[6];
    const float* bt = (const float*)d_in[7];
    float* out = (float*)d_out;

    __half *q_ptr, *k_ptr, *pt_h, *pr_h, *wq_h, *wk_h, *wt_h;
    float *g_ptr, *s_ptr;
    cudaGetSymbolAddress((void**)&q_ptr, g_q);
    cudaGetSymbolAddress((void**)&k_ptr, g_k);
    cudaGetSymbolAddress((void**)&pt_h,  g_pt);
    cudaGetSymbolAddress((void**)&pr_h,  g_pr);
    cudaGetSymbolAddress((void**)&wq_h,  g_wq);
    cudaGetSymbolAddress((void**)&wk_h,  g_wk);
    cudaGetSymbolAddress((void**)&wt_h,  g_wt);
    cudaGetSymbolAddress((void**)&g_ptr, g_gram);
    cudaGetSymbolAddress((void**)&s_ptr, g_rstar);

    // dynamic smem (3-stage), in bytes
    const int smemN = 3 * (TBM * AROW + TBK * BROW) * 2;   // 56832
    const int smemT = 3 * (TBK * ATROW + TBK * BROW) * 2;  // 52224
    cudaFuncSetAttribute(gemm_h<false, 0>,
        cudaFuncAttributeMaxDynamicSharedMemorySize, smemN);
    cudaFuncSetAttribute(gemm_h<true, 1>,
        cudaFuncAttributeMaxDynamicSharedMemorySize, smemT);
    cudaFuncSetAttribute(gemm_h<false, 2>,
        cudaFuncAttributeMaxDynamicSharedMemorySize, smemN);

    // 0) convert weights to half (wide) + fold features to [C][BL] half
    {
        long n8q = (long)CN * CN / 8;
        tohalf_kernel<<<(int)((n8q + 255) / 256), 256>>>(
            (const float4*)wq, (uint4*)wq_h, n8q);
        tohalf_kernel<<<(int)((n8q + 255) / 256), 256>>>(
            (const float4*)wk, (uint4*)wk_h, n8q);
        long n8t = (long)CN * 2 * CN / 8;
        tohalf_kernel<<<(int)((n8t + 255) / 256), 256>>>(
            (const float4*)wt, (uint4*)wt_h, n8t);
        tohalf_fold_kernel<<<dim3(CN, BN, 2), LN>>>(part_target, part_ref);
    }

    dim3 blk(256);

    // 1+2) dual conv: z=0: q = wq@pt + bq -> g_q rows [0,C); z=1: k = wk@pr + bk -> g_k
    gemm_h<false, 0><<<dim3(BL / TBN, CN / TBM, 2), blk, smemN>>>(
        wq_h, pt_h, q_ptr, CN, BL, CN, CN, BL, BL,
        0L, 0L, 0L,
        wk_h, pr_h, k_ptr,
        bq, bk, nullptr, nullptr);

    // 3) pixel squared norms
    pixnorm_kernel<<<dim3(BL / 32, 2), 256>>>();
    // 4) patch norms
    patchnorm_kernel<<<(2 * BL + 255) / 256, 256>>>();

    // 5) Gram per batch: G[l,m] = sum_c k[c, b*LN+l] q[c, b*LN+m]
    gemm_h<true, 1><<<dim3((LN + TBN - 1) / TBN, (LN + TBM - 1) / TBM, BN), blk, smemT>>>(
        k_ptr, q_ptr, g_ptr, LN, LN, CN, BL, BL, LN,
        (long)LN, (long)LN, (long)LN * LN,
        nullptr, nullptr, nullptr,
        nullptr, nullptr, nullptr, nullptr);

    // 6) R_star + argmax
    rstar_kernel<<<dim3(LN, BN), 128>>>();
    // 7) gather indices
    idx_kernel<<<(BL + 255) / 256, 256>>>();
    // 8) T_part -> g_q rows [C,2C)
    tpart_kernel<<<dim3(CN, BN), LN>>>();

    // 9) final: out[b][c][l] = (wt @ [q;T_part])[c, b*LN+l] * S + part_target
    gemm_h<false, 2><<<dim3(BL / TBN, CN / TBM, 1), blk, smemN>>>(
        wt_h, q_ptr, out, CN, BL, 2 * CN, 2 * CN, BL, 0,
        0L, 0L, 0L,
        nullptr, nullptr, nullptr,
        bt, nullptr, s_ptr, part_target);
}

// round 17
// speedup vs baseline: 1.2683x; 1.0450x over previous
#include <cuda_runtime.h>
#include <cuda_fp16.h>
#include <cstdint>

// Problem constants
#define BN 4
#define CN 2048
#define HN 24
#define WN 24
#define LN 576    // H*W
#define BL 2304   // BN*LN

// GEMM tile constants
#define TBM 128
#define TBN 128
#define TBK 32
#define AROW  40    // !TRANSA A smem row stride in halves (80B = 5x16B, odd phase)
#define ATROW 136   // TRANSA  A smem row stride in halves (272B = 17x16B)
#define BROW  136   // B smem row stride in halves

// ---------------- scratch (device globals; no allocation allowed) -----------
__device__ __half g_q[(long)2 * CN * BL];   // [2C][BL]: rows 0..C-1 = q, C..2C-1 = T_part
__device__ __half g_k[(long)CN * BL];       // [C][BL]
__device__ __half g_pt[(long)CN * BL];      // part_target: [C][BL]
__device__ __half g_pr[(long)CN * BL];      // part_ref: [C][BL]
__device__ __half g_wq[(long)CN * CN];
__device__ __half g_wk[(long)CN * CN];
__device__ __half g_wt[(long)CN * 2 * CN];
__device__ float g_gram[(long)BN * LN * LN];  // [B][L_ref][L_tgt]
__device__ float g_n2[2 * BL];
__device__ float g_pn[2 * BL];
__device__ float g_rstar[BL];
__device__ int   g_arg[BL];
__device__ int   g_idx[BL * 9];

__device__ __forceinline__ unsigned su(const void* p) {
    return (unsigned)__cvta_generic_to_shared(p);
}
#define CP16(d, s, sz) \
    asm volatile("cp.async.cg.shared.global [%0], [%1], 16, %2;" \
                 :: "r"(d), "l"(s), "r"(sz))

__device__ __forceinline__ void ldm_x4(uint32_t* r, unsigned a) {
    asm volatile("ldmatrix.sync.aligned.m8n8.x4.shared.b16 {%0,%1,%2,%3}, [%4];"
                 : "=r"(r[0]), "=r"(r[1]), "=r"(r[2]), "=r"(r[3]) : "r"(a));
}
__device__ __forceinline__ void ldm_x4_t(uint32_t* r, unsigned a) {
    asm volatile("ldmatrix.sync.aligned.m8n8.x4.trans.shared.b16 {%0,%1,%2,%3}, [%4];"
                 : "=r"(r[0]), "=r"(r[1]), "=r"(r[2]), "=r"(r[3]) : "r"(a));
}
#define MMA16(d, a, b0, b1) \
    asm volatile( \
        "mma.sync.aligned.m16n8k16.row.col.f32.f16.f16.f32 " \
        "{%0,%1,%2,%3},{%4,%5,%6,%7},{%8,%9},{%0,%1,%2,%3};" \
        : "+f"((d)[0]), "+f"((d)[1]), "+f"((d)[2]), "+f"((d)[3]) \
        : "r"((a)[0]), "r"((a)[1]), "r"((a)[2]), "r"((a)[3]), \
          "r"(b0), "r"(b1))

// ---------------- fp16 tensor-core GEMM (mma.sync m16n8k16) ------------------
// C[M,N] = op(A)[M,K] * B[K,N] (half, f32 accumulate). op(A)=A row-major
// [M,K] ld=ldA if !TRANSA, else A stored [K,*] ld=ldA with M-window columns.
// MODE 0 (dual conv): blockIdx.z selects (A,B,C,bias) pair; out(half) = acc+bias[row]
// MODE 1 (gram):  z = batch; A += z*sA (col offset), B += z*sB, C += z*sC; out(f32)=acc
// MODE 2 (final): out f32 at [b][row][l] where col = b*LN + l;
//                 out = (acc + bias[row]) * Sv[col] + resid[b*CN*LN + row*LN + l]
template<bool TRANSA, int MODE>
__global__ __launch_bounds__(256, 2)
void gemm_h(const __half* __restrict__ A, const __half* __restrict__ Bm,
            void* __restrict__ Cm_, int M, int N, int K,
            int ldA, int ldB, int ldC,
            long sA, long sB, long sC,
            const __half* __restrict__ A1, const __half* __restrict__ B1,
            void* __restrict__ C1,
            const float* __restrict__ bias0, const float* __restrict__ bias1,
            const float* __restrict__ Sv, const float* __restrict__ resid)
{
    extern __shared__ __half smem[];
    const int ASZ = TRANSA ? TBK * ATROW : TBM * AROW;
    const int BSZ = TBK * BROW;
    const int BUF = ASZ + BSZ;

    const int z = blockIdx.z;
    const float* bias = bias0;
    if (MODE == 0 && z == 1) { A = A1; Bm = B1; Cm_ = C1; bias = bias1; }
    if (MODE == 1) { A += z * sA; Bm += z * sB; }

    const int m0 = blockIdx.y * TBM;
    const int n0 = blockIdx.x * TBN;
    const int t  = threadIdx.x;
    const int lane = t & 31;
    const int w = t >> 5;
    const int wm = (w >> 1) * 32;
    const int wn = (w & 1) * 64;
    const int gid = lane >> 2;
    const int tig = lane & 3;

    float acc[2][8][4];
#pragma unroll
    for (int mt = 0; mt < 2; mt++)
#pragma unroll
        for (int nt = 0; nt < 8; nt++)
#pragma unroll
            for (int r = 0; r < 4; r++) acc[mt][nt][r] = 0.f;

    auto stage = [&](int kt, int buf) {
        __half* as = smem + buf * BUF;
        __half* bs = as + ASZ;
        const int k0 = kt * TBK;
        if (!TRANSA) {
#pragma unroll
            for (int i = 0; i < 2; i++) {
                int idx = t + i * 256;
                int m = idx >> 2, ch = idx & 3;        // 4 chunks x 8 halves
                const __half* src = A + (long)(m0 + m) * ldA + k0 + ch * 8;
                CP16(su(as + m * AROW + ch * 8), src, 16u);
            }
        } else {
#pragma unroll
            for (int i = 0; i < 2; i++) {
                int idx = t + i * 256;
                int kk = idx >> 4, ch = idx & 15;
                const __half* src = A + (long)(k0 + kk) * ldA + m0 + ch * 8;
                unsigned sz = (m0 + ch * 8 < M) ? 16u : 0u;
                CP16(su(as + kk * ATROW + ch * 8), src, sz);
            }
        }
#pragma unroll
        for (int i = 0; i < 2; i++) {
            int idx = t + i * 256;
            int kk = idx >> 4, ch = idx & 15;
            const __half* src = Bm + (long)(k0 + kk) * ldB + n0 + ch * 8;
            unsigned sz = (n0 + ch * 8 < N) ? 16u : 0u;
            CP16(su(bs + kk * BROW + ch * 8), src, sz);
        }
        asm volatile("cp.async.commit_group;");
    };

    const int nk = K / TBK;
    stage(0, 0);
    stage(1, 1);

    for (int it = 0; it < nk; it++) {
        if (it + 1 < nk)
            asm volatile("cp.async.wait_group 1;");
        else
            asm volatile("cp.async.wait_group 0;");
        __syncthreads();

        const __half* as = smem + (it % 3) * BUF;
        const __half* bs = as + ASZ;

#pragma unroll
        for (int ks = 0; ks < 2; ks++) {
            const int k = ks * 16;
            uint32_t af[2][4], bf[4][4];
            if (!TRANSA) {
#pragma unroll
                for (int mt = 0; mt < 2; mt++) {
                    unsigned a = su(as + (wm + mt * 16 + (lane & 15)) * AROW
                                       + k + (lane >> 4) * 8);
                    ldm_x4(af[mt], a);
                }
            } else {
#pragma unroll
                for (int mt = 0; mt < 2; mt++) {
                    unsigned a = su(as + (k + (lane & 7) + ((lane >> 4) & 1) * 8) * ATROW
                                       + wm + mt * 16 + ((lane >> 3) & 1) * 8);
                    ldm_x4_t(af[mt], a);
                }
            }
#pragma unroll
            for (int g = 0; g < 4; g++) {
                unsigned a = su(bs + (k + (lane & 7) + ((lane >> 3) & 1) * 8) * BROW
                                   + wn + g * 16 + ((lane >> 4) & 1) * 8);
                ldm_x4_t(bf[g], a);
            }
#pragma unroll
            for (int mt = 0; mt < 2; mt++)
#pragma unroll
                for (int nt = 0; nt < 8; nt++) {
                    int g = nt >> 1, h = (nt & 1) * 2;
                    MMA16(acc[mt][nt], af[mt], bf[g][h], bf[g][h + 1]);
                }
        }
        if (it + 2 < nk) stage(it + 2, (it + 2) % 3);
    }

    // ---- epilogue ----
#pragma unroll
    for (int mt = 0; mt < 2; mt++) {
#pragma unroll
        for (int rp = 0; rp < 2; rp++) {
            int row = m0 + wm + mt * 16 + gid + rp * 8;
            if (MODE == 1 && row >= M) continue;
            float bv = (MODE != 1) ? bias[row] : 0.f;
#pragma unroll
            for (int nt = 0; nt < 8; nt++) {
                int col = n0 + wn + nt * 8 + tig * 2;
                float v0 = acc[mt][nt][rp * 2 + 0];
                float v1 = acc[mt][nt][rp * 2 + 1];
                if (MODE == 0) {
                    __half* C = (__half*)Cm_;
                    *(__half2*)(C + (long)row * ldC + col) =
                        __floats2half2_rn(v0 + bv, v1 + bv);
                } else if (MODE == 1) {
                    if (col >= N) continue;
                    float* C = (float*)Cm_ + z * sC;
                    *(float2*)(C + (long)row * ldC + col) = make_float2(v0, v1);
                } else {
                    int b = col / LN;
                    int l = col - b * LN;
                    float* C = (float*)Cm_ + (long)b * CN * LN + (long)row * LN + l;
                    const float* rs = resid + (long)b * CN * LN + (long)row * LN + l;
                    float2 rv = *(const float2*)rs;
                    float2 o;
                    o.x = (v0 + bv) * Sv[col + 0] + rv.x;
                    o.y = (v1 + bv) * Sv[col + 1] + rv.y;
                    *(float2*)C = o;
                }
            }
        }
    }
}

// ---------------- merged f32 -> f16 weight conversion ------------------------
// grid-stride over all three weight tensors in one launch
__global__ __launch_bounds__(256)
void tohalf3_kernel(const float4* __restrict__ wq, const float4* __restrict__ wk,
                    const float4* __restrict__ wt,
                    uint4* __restrict__ dq, uint4* __restrict__ dk,
                    uint4* __restrict__ dt, long n8q, long n8t)
{
    long i = (long)blockIdx.x * blockDim.x + threadIdx.x;
    long stride = (long)gridDim.x * blockDim.x;
    long total = 2 * n8q + n8t;
    for (; i < total; i += stride) {
        const float4* s; uint4* d; long j;
        if (i < n8q)          { s = wq; d = dq; j = i; }
        else if (i < 2 * n8q) { s = wk; d = dk; j = i - n8q; }
        else                  { s = wt; d = dt; j = i - 2 * n8q; }
        float4 a = s[j * 2 + 0];
        float4 b = s[j * 2 + 1];
        __half2 h0 = __floats2half2_rn(a.x, a.y);
        __half2 h1 = __floats2half2_rn(a.z, a.w);
        __half2 h2 = __floats2half2_rn(b.x, b.y);
        __half2 h3 = __floats2half2_rn(b.z, b.w);
        uint4 o;
        o.x = *(uint32_t*)&h0; o.y = *(uint32_t*)&h1;
        o.z = *(uint32_t*)&h2; o.w = *(uint32_t*)&h3;
        d[j] = o;
    }
}

// ---------------- f32 [B][C][L] -> f16 [C][B*L], vectorized ------------------
// grid (CN, 2), block 576: thread t handles float4 at (b = t/144, l4 = t%144)
__global__ void tohalf_fold_kernel(const float* __restrict__ pt,
                                   const float* __restrict__ pr)
{
    const int c = blockIdx.x;
    const float* src = blockIdx.y ? pr : pt;
    __half* dst = blockIdx.y ? g_pr : g_pt;
    const int t = threadIdx.x;
    const int b = t / 144;
    const int l4 = (t - b * 144) * 4;
    float4 v = *(const float4*)(src + ((long)b * CN + c) * LN + l4);
    __half2 h0 = __floats2half2_rn(v.x, v.y);
    __half2 h1 = __floats2half2_rn(v.z, v.w);
    uint2 o;
    o.x = *(uint32_t*)&h0; o.y = *(uint32_t*)&h1;
    *(uint2*)(dst + (long)c * BL + b * LN + l4) = o;
}

// ---------------- pixel squared norms ---------------------------------------
// grid (BL/32, 2), block 256 = 32 cols x 8 c-slices
__global__ void pixnorm_kernel()
{
    const int which = blockIdx.y;   // 0 = k, 1 = q
    const int tid = threadIdx.x;
    const int lane = tid & 31;
    const int cs = tid >> 5;
    const int j = blockIdx.x * 32 + lane;
    const __half* src = which ? g_q : g_k;
    float s = 0.f;
    for (int c = cs; c < CN; c += 8) {
        float v = __half2float(src[(long)c * BL + j]);
        s += v * v;
    }
    __shared__ float red[256];
    red[tid] = s;
    __syncthreads();
    for (int off = 128; off >= 32; off >>= 1) {
        if (tid < off) red[tid] += red[tid + off];
        __syncthreads();
    }
    if (tid < 32) g_n2[which * BL + j] = red[tid];
}

// ---------------- patch norms ------------------------------------------------
__global__ void patchnorm_kernel()
{
    int idx = blockIdx.x * blockDim.x + threadIdx.x;
    if (idx >= 2 * BL) return;
    int which = idx / BL;
    int rem = idx % BL;
    int b = rem / LN;
    int l = rem % LN;
    int li = l / WN, lj = l % WN;
    const float* n2 = g_n2 + which * BL + b * LN;
    float s = 0.f;
#pragma unroll
    for (int di = -1; di <= 1; di++)
#pragma unroll
        for (int dj = -1; dj <= 1; dj++) {
            int i2 = li + di, j2 = lj + dj;
            if (i2 >= 0 && i2 < HN && j2 >= 0 && j2 < WN)
                s += n2[i2 * WN + j2];
        }
    g_pn[idx] = fmaxf(sqrtf(s), 1e-12f);
}

// ---------------- R + argmax over ref positions ------------------------------
__global__ void rstar_kernel()
{
    const int m = blockIdx.x;
    const int b = blockIdx.y;
    const int mi = m / WN, mj = m % WN;
    const float* G = g_gram + (long)b * LN * LN;
    const float* pnk = g_pn + b * LN;
    const int tid = threadIdx.x;

    float best = -1e30f;
    int barg = 0;
    for (int l = tid; l < LN; l += 128) {
        int li = l / WN, lj = l % WN;
        float s = 0.f;
#pragma unroll
        for (int di = -1; di <= 1; di++)
#pragma unroll
            for (int dj = -1; dj <= 1; dj++) {
                int li2 = li + di, lj2 = lj + dj;
                int mi2 = mi + di, mj2 = mj + dj;
                if (li2 >= 0 && li2 < HN && lj2 >= 0 && lj2 < WN &&
                    mi2 >= 0 && mi2 < HN && mj2 >= 0 && mj2 < WN) {
                    int off = di * WN + dj;
                    s += G[(long)(l + off) * LN + (m + off)];
                }
            }
        float v = s / pnk[l];
        if (v > best) { best = v; barg = l; }
    }
    __shared__ float sv[128];
    __shared__ int si[128];
    sv[tid] = best; si[tid] = barg;
    __syncthreads();
    for (int off = 64; off >= 1; off >>= 1) {
        if (tid < off) {
            if (sv[tid + off] > sv[tid] ||
                (sv[tid + off] == sv[tid] && si[tid + off] < si[tid])) {
                sv[tid] = sv[tid + off];
                si[tid] = si[tid + off];
            }
        }
        __syncthreads();
    }
    if (tid == 0) {
        g_rstar[b * LN + m] = sv[0] / g_pn[BL + b * LN + m];
        g_arg[b * LN + m] = si[0];
    }
}

// ---------------- gather-index precompute ------------------------------------
__global__ void idx_kernel()
{
    int idx = blockIdx.x * blockDim.x + threadIdx.x;
    if (idx >= BL) return;
    int b = idx / LN;
    int p = idx % LN;
    int pi = p / WN, pj = p % WN;
#pragma unroll
    for (int j = 0; j < 9; j++) {
        int di = j / 3 - 1, dj = j % 3 - 1;
        int mi = pi - di, mj = pj - dj;
        int id = -1;
        if (mi >= 0 && mi < HN && mj >= 0 && mj < WN) {
            int a = g_arg[b * LN + mi * WN + mj];
            int ai = a / WN + di, aj = a % WN + dj;
            if (ai >= 0 && ai < HN && aj >= 0 && aj < WN)
                id = ai * WN + aj;
        }
        g_idx[(long)(b * LN + p) * 9 + j] = id;
    }
}

// ---------------- build T_part (half) into rows [C,2C) of g_q ----------------
// grid (CN/16, BN), block 576. Indices depend only on (b,p): load once into
// registers, loop over 16 c-rows.
#define TPC 16
__global__ void tpart_kernel()
{
    const int c0 = blockIdx.x * TPC;
    const int b = blockIdx.y;
    const int p = threadIdx.x;
    const int* idxr = g_idx + ((long)b * LN + p) * 9;
    int ids[9];
#pragma unroll
    for (int j = 0; j < 9; j++) ids[j] = idxr[j];

#pragma unroll 1
    for (int cc = 0; cc < TPC; cc++) {
        const int c = c0 + cc;
        const __half* krow = g_k + (long)c * BL + b * LN;
        float s = 0.f;
#pragma unroll
        for (int j = 0; j < 9; j++) {
            int id = ids[j];
            if (id >= 0) s += __half2float(krow[id]);
        }
        g_q[(long)(CN + c) * BL + b * LN + p] = __float2half_rn(s * (1.f / 9.f));
    }
}

// ---------------- host launch ------------------------------------------------
extern "C" void kernel_launch(void* const* d_in, const int* in_sizes, int n_in,
                              void* d_out, int out_size)
{
    const float* part_ref    = (const float*)d_in[0];
    const float* part_target = (const float*)d_in[1];
    const float* wq = (const float*)d_in[2];
    const float* bq = (const float*)d_in[3];
    const float* wk = (const float*)d_in[4];
    const float* bk = (const float*)d_in[5];
    const float* wt = (const float*)d_in[6];
    const float* bt = (const float*)d_in[7];
    float* out = (float*)d_out;

    __half *q_ptr, *k_ptr, *pt_h, *pr_h, *wq_h, *wk_h, *wt_h;
    float *g_ptr, *s_ptr;
    cudaGetSymbolAddress((void**)&q_ptr, g_q);
    cudaGetSymbolAddress((void**)&k_ptr, g_k);
    cudaGetSymbolAddress((void**)&pt_h,  g_pt);
    cudaGetSymbolAddress((void**)&pr_h,  g_pr);
    cudaGetSymbolAddress((void**)&wq_h,  g_wq);
    cudaGetSymbolAddress((void**)&wk_h,  g_wk);
    cudaGetSymbolAddress((void**)&wt_h,  g_wt);
    cudaGetSymbolAddress((void**)&g_ptr, g_gram);
    cudaGetSymbolAddress((void**)&s_ptr, g_rstar);

    // dynamic smem (3-stage), in bytes
    const int smemN = 3 * (TBM * AROW + TBK * BROW) * 2;   // 56832
    const int smemT = 3 * (TBK * ATROW + TBK * BROW) * 2;  // 52224
    cudaFuncSetAttribute(gemm_h<false, 0>,
        cudaFuncAttributeMaxDynamicSharedMemorySize, smemN);
    cudaFuncSetAttribute(gemm_h<true, 1>,
        cudaFuncAttributeMaxDynamicSharedMemorySize, smemT);
    cudaFuncSetAttribute(gemm_h<false, 2>,
        cudaFuncAttributeMaxDynamicSharedMemorySize, smemN);

    // 0) convert weights (merged) + fold features to [C][BL] half (vectorized)
    {
        long n8q = (long)CN * CN / 8;
        long n8t = (long)CN * 2 * CN / 8;
        tohalf3_kernel<<<4096, 256>>>(
            (const float4*)wq, (const float4*)wk, (const float4*)wt,
            (uint4*)wq_h, (uint4*)wk_h, (uint4*)wt_h, n8q, n8t);
        tohalf_fold_kernel<<<dim3(CN, 2), LN>>>(part_target, part_ref);
    }

    dim3 blk(256);

    // 1+2) dual conv: z=0: q = wq@pt + bq -> g_q rows [0,C); z=1: k = wk@pr + bk -> g_k
    gemm_h<false, 0><<<dim3(BL / TBN, CN / TBM, 2), blk, smemN>>>(
        wq_h, pt_h, q_ptr, CN, BL, CN, CN, BL, BL,
        0L, 0L, 0L,
        wk_h, pr_h, k_ptr,
        bq, bk, nullptr, nullptr);

    // 3) pixel squared norms
    pixnorm_kernel<<<dim3(BL / 32, 2), 256>>>();
    // 4) patch norms
    patchnorm_kernel<<<(2 * BL + 255) / 256, 256>>>();

    // 5) Gram per batch: G[l,m] = sum_c k[c, b*LN+l] q[c, b*LN+m]
    gemm_h<true, 1><<<dim3((LN + TBN - 1) / TBN, (LN + TBM - 1) / TBM, BN), blk, smemT>>>(
        k_ptr, q_ptr, g_ptr, LN, LN, CN, BL, BL, LN,
        (long)LN, (long)LN, (long)LN * LN,
        nullptr, nullptr, nullptr,
        nullptr, nullptr, nullptr, nullptr);

    // 6) R_star + argmax
    rstar_kernel<<<dim3(LN, BN), 128>>>();
    // 7) gather indices
    idx_kernel<<<(BL + 255) / 256, 256>>>();
    // 8) T_part -> g_q rows [C,2C)
    tpart_kernel<<<dim3(CN / TPC, BN), LN>>>();

    // 9) final: out[b][c][l] = (wt @ [q;T_part])[c, b*LN+l] * S + part_target
    gemm_h<false, 2><<<dim3(BL / TBN, CN / TBM, 1), blk, smemN>>>(
        wt_h, q_ptr, out, CN, BL, 2 * CN, 2 * CN, BL, 0,
        0L, 0L, 0L,
        nullptr, nullptr, nullptr,
        bt, nullptr, s_ptr, part_target);
}